// round 12
// baseline (speedup 1.0000x reference)
#include <cuda_runtime.h>
#include <math.h>

// ---------------- problem constants ----------------
#define NN 2048
#define CD 512
#define DD 128
#define KP 1024
#define NW 64            // 2048 bits / 32
#define NWP 32           // 1024 bits / 32
#define INVT 14.285714285714286f

// ---------------- device scratch ----------------
__device__ __align__(16) float g_fet[NN*DD];
__device__ __align__(16) float g_fes[NN*DD];
__device__ unsigned g_bits[NN*NW];
__device__ unsigned g_bitsp[KP*NWP];
__device__ int   g_deg[NN];
__device__ float g_dinvp[KP];
__device__ __align__(16) float g_fg[2][NN*DD];     // [0]=teacher,[1]=student
__device__ __align__(16) float g_fp[2][KP*DD];
__device__ __align__(16) float g_cat[2][NN*384];   // concat [h0|h1|h2]
__device__ __align__(16) float g_catp[2][KP*256];  // pooled concat [newh|h1p]
__device__ float g_scores[NN];
__device__ int   g_idx[KP];
__device__ float g_vals[KP];
__device__ __align__(16) float g_part[16][NN*DD];  // split-K partials
__device__ float g_rp[16*NN], g_cp[16*NN], g_diag[NN];
__device__ float g_rp2[8*KP], g_cp2[8*KP], g_diagp[KP];

// ---------------- tf32 helpers ----------------
__device__ __forceinline__ unsigned f2tf(float x) {
    unsigned r; asm("cvt.rna.tf32.f32 %0, %1;" : "=r"(r) : "f"(x)); return r;
}
__device__ __forceinline__ void mma8(float c[4], unsigned a0, unsigned a1, unsigned a2, unsigned a3,
                                     unsigned b0, unsigned b1) {
    asm volatile("mma.sync.aligned.m16n8k8.row.col.f32.tf32.tf32.f32 "
                 "{%0,%1,%2,%3}, {%4,%5,%6,%7}, {%8,%9}, {%0,%1,%2,%3};\n"
                 : "+f"(c[0]), "+f"(c[1]), "+f"(c[2]), "+f"(c[3])
                 : "r"(a0), "r"(a1), "r"(a2), "r"(a3), "r"(b0), "r"(b1));
}

// ---- MMA over one 16-K stage, 3-pass tf32 split (fp32-accurate), raw-float smem ----
__device__ __forceinline__ void mma_tile_split(
    float acc[4][4][4], const float (*__restrict__ sa)[132], const float (*__restrict__ sb)[136],
    int wm, int wn, int grp, int qid)
{
#pragma unroll
    for (int kk = 0; kk < 16; kk += 8) {
        float araw[4][4], braw[4][2];
        unsigned ah[4][4], bh[4][2];
#pragma unroll
        for (int t = 0; t < 4; t++) {
            int r = wm*64 + t*16 + grp;
            araw[t][0] = sa[kk+qid][r];   araw[t][1] = sa[kk+qid][r+8];
            araw[t][2] = sa[kk+qid+4][r]; araw[t][3] = sa[kk+qid+4][r+8];
#pragma unroll
            for (int j = 0; j < 4; j++) ah[t][j] = f2tf(araw[t][j]);
        }
#pragma unroll
        for (int u = 0; u < 4; u++) {
            int c = wn*32 + u*8 + grp;
            braw[u][0] = sb[kk+qid][c]; braw[u][1] = sb[kk+qid+4][c];
            bh[u][0] = f2tf(braw[u][0]); bh[u][1] = f2tf(braw[u][1]);
        }
#pragma unroll
        for (int t = 0; t < 4; t++)
#pragma unroll
            for (int u = 0; u < 4; u++)
                mma8(acc[t][u], ah[t][0],ah[t][1],ah[t][2],ah[t][3], bh[u][0],bh[u][1]);
        {
            unsigned bl[4][2];
#pragma unroll
            for (int u = 0; u < 4; u++) {
                bl[u][0] = f2tf(braw[u][0] - __uint_as_float(bh[u][0]));
                bl[u][1] = f2tf(braw[u][1] - __uint_as_float(bh[u][1]));
            }
#pragma unroll
            for (int t = 0; t < 4; t++)
#pragma unroll
                for (int u = 0; u < 4; u++)
                    mma8(acc[t][u], ah[t][0],ah[t][1],ah[t][2],ah[t][3], bl[u][0],bl[u][1]);
        }
        {
            unsigned al[4][4];
#pragma unroll
            for (int t = 0; t < 4; t++)
#pragma unroll
                for (int j = 0; j < 4; j++)
                    al[t][j] = f2tf(araw[t][j] - __uint_as_float(ah[t][j]));
#pragma unroll
            for (int t = 0; t < 4; t++)
#pragma unroll
                for (int u = 0; u < 4; u++)
                    mma8(acc[t][u], al[t][0],al[t][1],al[t][2],al[t][3], bh[u][0],bh[u][1]);
        }
    }
}

// ---- MMA over one 16-K stage, single-pass, pre-converted tf32 smem ----
__device__ __forceinline__ void mma_tile_1p_u(
    float acc[4][4][4], const unsigned (*__restrict__ sa)[132], const unsigned (*__restrict__ sb)[136],
    int wm, int wn, int grp, int qid)
{
#pragma unroll
    for (int kk = 0; kk < 16; kk += 8) {
        unsigned ah[4][4], bh[4][2];
#pragma unroll
        for (int t = 0; t < 4; t++) {
            int r = wm*64 + t*16 + grp;
            ah[t][0] = sa[kk+qid][r];   ah[t][1] = sa[kk+qid][r+8];
            ah[t][2] = sa[kk+qid+4][r]; ah[t][3] = sa[kk+qid+4][r+8];
        }
#pragma unroll
        for (int u = 0; u < 4; u++) {
            int c = wn*32 + u*8 + grp;
            bh[u][0] = sb[kk+qid][c]; bh[u][1] = sb[kk+qid+4][c];
        }
#pragma unroll
        for (int t = 0; t < 4; t++)
#pragma unroll
            for (int u = 0; u < 4; u++)
                mma8(acc[t][u], ah[t][0],ah[t][1],ah[t][2],ah[t][3], bh[u][0],bh[u][1]);
    }
}

// ---------------- NN GEMM, split-tf32, double-buffered: C[M,128]=A[M,K]@B[K,128] ----------------
// grid (M/128, K/Kchunk, 2), block 256
__global__ void __launch_bounds__(256) k_mma_nn(
    const float* __restrict__ A0, const float* __restrict__ A1, int lda,
    const float* __restrict__ B,
    float* __restrict__ P, int M, int Kchunk, int nsl)
{
    __shared__ float sA[2][16][132];
    __shared__ float sB[2][16][136];
    const float* A = blockIdx.z ? A1 : A0;
    const int row0 = blockIdx.x * 128;
    const int k0 = blockIdx.y * Kchunk;
    float* Pout = P + (size_t)(blockIdx.z * nsl + blockIdx.y) * ((size_t)M * 128);
    const int tid = threadIdx.x, lane = tid & 31, w = tid >> 5;
    const int wm = w >> 2, wn = w & 3, grp = lane >> 2, qid = lane & 3;

    float acc[4][4][4];
#pragma unroll
    for (int t = 0; t < 4; t++)
#pragma unroll
        for (int u = 0; u < 4; u++)
#pragma unroll
            for (int v = 0; v < 4; v++) acc[t][u][v] = 0.f;

    const int ar = tid >> 1, akb = (tid & 1) * 8;
    const int bk = tid >> 4, bnb = (tid & 15) * 8;
    float ra[8], rb[8];

    {
        const float* as_ = A + (size_t)(row0 + ar) * lda + k0 + akb;
        float4 a0 = *(const float4*)as_, a1 = *(const float4*)(as_ + 4);
        ra[0]=a0.x; ra[1]=a0.y; ra[2]=a0.z; ra[3]=a0.w; ra[4]=a1.x; ra[5]=a1.y; ra[6]=a1.z; ra[7]=a1.w;
        const float* bs_ = B + (size_t)(k0 + bk) * 128 + bnb;
        float4 b0 = *(const float4*)bs_, b1 = *(const float4*)(bs_ + 4);
        rb[0]=b0.x; rb[1]=b0.y; rb[2]=b0.z; rb[3]=b0.w; rb[4]=b1.x; rb[5]=b1.y; rb[6]=b1.z; rb[7]=b1.w;
    }
    const int nIter = Kchunk / 16;
#pragma unroll
    for (int i = 0; i < 8; i++) sA[0][akb + i][ar] = ra[i];
#pragma unroll
    for (int i = 0; i < 8; i++) sB[0][bk][bnb + i] = rb[i];
    __syncthreads();

    for (int it = 0; it < nIter; ++it) {
        const int cur = it & 1;
        const bool more = (it + 1) < nIter;
        if (more) {
            int kt = k0 + (it + 1) * 16;
            const float* as_ = A + (size_t)(row0 + ar) * lda + kt + akb;
            float4 a0 = *(const float4*)as_, a1 = *(const float4*)(as_ + 4);
            ra[0]=a0.x; ra[1]=a0.y; ra[2]=a0.z; ra[3]=a0.w; ra[4]=a1.x; ra[5]=a1.y; ra[6]=a1.z; ra[7]=a1.w;
            const float* bs_ = B + (size_t)(kt + bk) * 128 + bnb;
            float4 b0 = *(const float4*)bs_, b1 = *(const float4*)(bs_ + 4);
            rb[0]=b0.x; rb[1]=b0.y; rb[2]=b0.z; rb[3]=b0.w; rb[4]=b1.x; rb[5]=b1.y; rb[6]=b1.z; rb[7]=b1.w;
        }
        mma_tile_split(acc, sA[cur], sB[cur], wm, wn, grp, qid);
        if (more) {
#pragma unroll
            for (int i = 0; i < 8; i++) sA[cur ^ 1][akb + i][ar] = ra[i];
#pragma unroll
            for (int i = 0; i < 8; i++) sB[cur ^ 1][bk][bnb + i] = rb[i];
        }
        __syncthreads();
    }
#pragma unroll
    for (int t = 0; t < 4; t++) {
        int r = row0 + wm * 64 + t * 16 + grp;
#pragma unroll
        for (int u = 0; u < 4; u++) {
            int c = wn * 32 + u * 8 + qid * 2;
            *(float2*)(Pout + (size_t)r * 128 + c)       = make_float2(acc[t][u][0], acc[t][u][1]);
            *(float2*)(Pout + (size_t)(r + 8) * 128 + c) = make_float2(acc[t][u][2], acc[t][u][3]);
        }
    }
}

// ---------------- adjacency gram (SYMMETRIC): bits = (F F^T > 0) + integer degree atomics ----------------
// grid (136), block 256.  Off-diagonal tiles also emit the transposed bit-block.
__global__ void __launch_bounds__(256) k_mma_nt_adj(const float* __restrict__ F)
{
    __shared__ float sA[2][16][132];
    __shared__ float sB[2][16][136];
    __shared__ unsigned srow[128][5];
    int i = blockIdx.x;
    int by = (int)((sqrtf(8.f * i + 1.f) - 1.f) * 0.5f);
    while ((by + 1) * (by + 2) / 2 <= i) by++;
    while (by * (by + 1) / 2 > i) by--;
    int bx = i - by * (by + 1) / 2;
    const int row0 = bx * 128, col0 = by * 128;
    const int tid = threadIdx.x, lane = tid & 31, w = tid >> 5;
    const int wm = w >> 2, wn = w & 3, grp = lane >> 2, qid = lane & 3;

    float acc[4][4][4];
#pragma unroll
    for (int t = 0; t < 4; t++)
#pragma unroll
        for (int u = 0; u < 4; u++)
#pragma unroll
            for (int v = 0; v < 4; v++) acc[t][u][v] = 0.f;

    const int fr = tid >> 1, fkb = (tid & 1) * 8;
    float ra[8], rb[8];
    {
        const float* as_ = F + (size_t)(row0 + fr) * 128 + fkb;
        float4 a0 = *(const float4*)as_, a1 = *(const float4*)(as_ + 4);
        ra[0]=a0.x; ra[1]=a0.y; ra[2]=a0.z; ra[3]=a0.w; ra[4]=a1.x; ra[5]=a1.y; ra[6]=a1.z; ra[7]=a1.w;
        const float* bs_ = F + (size_t)(col0 + fr) * 128 + fkb;
        float4 b0 = *(const float4*)bs_, b1 = *(const float4*)(bs_ + 4);
        rb[0]=b0.x; rb[1]=b0.y; rb[2]=b0.z; rb[3]=b0.w; rb[4]=b1.x; rb[5]=b1.y; rb[6]=b1.z; rb[7]=b1.w;
    }
#pragma unroll
    for (int i2 = 0; i2 < 8; i2++) sA[0][fkb + i2][fr] = ra[i2];
#pragma unroll
    for (int i2 = 0; i2 < 8; i2++) sB[0][fkb + i2][fr] = rb[i2];
    __syncthreads();

    for (int it = 0; it < 8; ++it) {
        const int cur = it & 1;
        const bool more = it < 7;
        if (more) {
            int kt = (it + 1) * 16;
            const float* as_ = F + (size_t)(row0 + fr) * 128 + kt + fkb;
            float4 a0 = *(const float4*)as_, a1 = *(const float4*)(as_ + 4);
            ra[0]=a0.x; ra[1]=a0.y; ra[2]=a0.z; ra[3]=a0.w; ra[4]=a1.x; ra[5]=a1.y; ra[6]=a1.z; ra[7]=a1.w;
            const float* bs_ = F + (size_t)(col0 + fr) * 128 + kt + fkb;
            float4 b0 = *(const float4*)bs_, b1 = *(const float4*)(bs_ + 4);
            rb[0]=b0.x; rb[1]=b0.y; rb[2]=b0.z; rb[3]=b0.w; rb[4]=b1.x; rb[5]=b1.y; rb[6]=b1.z; rb[7]=b1.w;
        }
        mma_tile_split(acc, sA[cur], sB[cur], wm, wn, grp, qid);
        if (more) {
#pragma unroll
            for (int i2 = 0; i2 < 8; i2++) sA[cur ^ 1][fkb + i2][fr] = ra[i2];
#pragma unroll
            for (int i2 = 0; i2 < 8; i2++) sB[cur ^ 1][fkb + i2][fr] = rb[i2];
        }
        __syncthreads();
    }
#pragma unroll
    for (int t = 0; t < 4; t++)
#pragma unroll
        for (int h = 0; h < 2; h++) {
            unsigned m = 0;
#pragma unroll
            for (int u = 0; u < 4; u++)
#pragma unroll
                for (int vv = 0; vv < 2; vv++)
                    if (acc[t][u][h * 2 + vv] > 0.f) m |= 1u << (u * 8 + qid * 2 + vv);
            m |= __shfl_xor_sync(~0u, m, 1);
            m |= __shfl_xor_sync(~0u, m, 2);
            if (qid == 0) {
                int rl = wm * 64 + t * 16 + h * 8 + grp;
                g_bits[(size_t)(row0 + rl) * NW + (col0 >> 5) + wn] = m;
                srow[rl][wn] = m;
                atomicAdd(&g_deg[row0 + rl], __popc(m));
            }
        }
    if (row0 != col0) {
        __syncthreads();
        for (int idx = tid; idx < 512; idx += 256) {
            int j = idx >> 2, wq = idx & 3;
            unsigned o = 0;
#pragma unroll
            for (int b = 0; b < 32; b++)
                o |= ((srow[wq * 32 + b][j >> 5] >> (j & 31)) & 1u) << b;
            g_bits[(size_t)(col0 + j) * NW + (row0 >> 5) + wq] = o;
            atomicAdd(&g_deg[col0 + j], __popc(o));
        }
    }
}

// ---------------- NCE gram: exp row/col partial sums + diag; pre-converted tf32 smem ----------------
// grid (n/128, n/128), block 256, 2 CTAs/SM
__global__ void __launch_bounds__(256, 2) k_mma_nt_nce(
    const float* __restrict__ F, const float* __restrict__ Gm, int n,
    float* __restrict__ RP, float* __restrict__ CP, float* __restrict__ diag)
{
    __shared__ unsigned sA[2][16][132];
    __shared__ unsigned sB[2][16][136];
    const int row0 = blockIdx.x * 128, col0 = blockIdx.y * 128;
    const int tid = threadIdx.x, lane = tid & 31, w = tid >> 5;
    const int wm = w >> 2, wn = w & 3, grp = lane >> 2, qid = lane & 3;

    float acc[4][4][4];
#pragma unroll
    for (int t = 0; t < 4; t++)
#pragma unroll
        for (int u = 0; u < 4; u++)
#pragma unroll
            for (int v = 0; v < 4; v++) acc[t][u][v] = 0.f;

    const int fr = tid >> 1, fkb = (tid & 1) * 8;
    float ra[8], rb[8];
    {
        const float* as_ = F + (size_t)(row0 + fr) * 128 + fkb;
        float4 a0 = *(const float4*)as_, a1 = *(const float4*)(as_ + 4);
        ra[0]=a0.x; ra[1]=a0.y; ra[2]=a0.z; ra[3]=a0.w; ra[4]=a1.x; ra[5]=a1.y; ra[6]=a1.z; ra[7]=a1.w;
        const float* bs_ = Gm + (size_t)(col0 + fr) * 128 + fkb;
        float4 b0 = *(const float4*)bs_, b1 = *(const float4*)(bs_ + 4);
        rb[0]=b0.x; rb[1]=b0.y; rb[2]=b0.z; rb[3]=b0.w; rb[4]=b1.x; rb[5]=b1.y; rb[6]=b1.z; rb[7]=b1.w;
    }
#pragma unroll
    for (int i = 0; i < 8; i++) sA[0][fkb + i][fr] = f2tf(ra[i]);
#pragma unroll
    for (int i = 0; i < 8; i++) sB[0][fkb + i][fr] = f2tf(rb[i]);
    __syncthreads();

    for (int it = 0; it < 8; ++it) {
        const int cur = it & 1;
        const bool more = it < 7;
        if (more) {
            int kt = (it + 1) * 16;
            const float* as_ = F + (size_t)(row0 + fr) * 128 + kt + fkb;
            float4 a0 = *(const float4*)as_, a1 = *(const float4*)(as_ + 4);
            ra[0]=a0.x; ra[1]=a0.y; ra[2]=a0.z; ra[3]=a0.w; ra[4]=a1.x; ra[5]=a1.y; ra[6]=a1.z; ra[7]=a1.w;
            const float* bs_ = Gm + (size_t)(col0 + fr) * 128 + kt + fkb;
            float4 b0 = *(const float4*)bs_, b1 = *(const float4*)(bs_ + 4);
            rb[0]=b0.x; rb[1]=b0.y; rb[2]=b0.z; rb[3]=b0.w; rb[4]=b1.x; rb[5]=b1.y; rb[6]=b1.z; rb[7]=b1.w;
        }
        mma_tile_1p_u(acc, sA[cur], sB[cur], wm, wn, grp, qid);
        if (more) {
#pragma unroll
            for (int i = 0; i < 8; i++) sA[cur ^ 1][fkb + i][fr] = f2tf(ra[i]);
#pragma unroll
            for (int i = 0; i < 8; i++) sB[cur ^ 1][fkb + i][fr] = f2tf(rb[i]);
        }
        __syncthreads();
    }

    if (blockIdx.x == blockIdx.y) {
#pragma unroll
        for (int t = 0; t < 4; t++)
#pragma unroll
            for (int u = 0; u < 4; u++)
#pragma unroll
                for (int v = 0; v < 4; v++) {
                    int r = wm * 64 + t * 16 + (v >> 1) * 8 + grp;
                    int c = wn * 32 + u * 8 + qid * 2 + (v & 1);
                    if (r == c) diag[row0 + r] = acc[t][u][v];
                }
    }
#pragma unroll
    for (int t = 0; t < 4; t++)
#pragma unroll
        for (int u = 0; u < 4; u++)
#pragma unroll
            for (int v = 0; v < 4; v++)
                acc[t][u][v] = __expf(acc[t][u][v] * INVT - INVT);

    float* red = (float*)sA;
#pragma unroll
    for (int t = 0; t < 4; t++)
#pragma unroll
        for (int h = 0; h < 2; h++) {
            float rs = 0.f;
#pragma unroll
            for (int u = 0; u < 4; u++)
#pragma unroll
                for (int vv = 0; vv < 2; vv++) rs += acc[t][u][h * 2 + vv];
            rs += __shfl_xor_sync(~0u, rs, 1);
            rs += __shfl_xor_sync(~0u, rs, 2);
            if (qid == 0) red[wn * 128 + wm * 64 + t * 16 + h * 8 + grp] = rs;
        }
    __syncthreads();
    if (tid < 128)
        RP[(size_t)blockIdx.y * n + row0 + tid] = red[tid] + red[128 + tid] + red[256 + tid] + red[384 + tid];
    __syncthreads();
#pragma unroll
    for (int u = 0; u < 4; u++)
#pragma unroll
        for (int vv = 0; vv < 2; vv++) {
            float cs = 0.f;
#pragma unroll
            for (int t = 0; t < 4; t++)
#pragma unroll
                for (int h = 0; h < 2; h++) cs += acc[t][u][h * 2 + vv];
            cs += __shfl_xor_sync(~0u, cs, 4);
            cs += __shfl_xor_sync(~0u, cs, 8);
            cs += __shfl_xor_sync(~0u, cs, 16);
            if (grp == 0) red[wm * 128 + wn * 32 + u * 8 + qid * 2 + vv] = cs;
        }
    __syncthreads();
    if (tid < 128)
        CP[(size_t)blockIdx.x * n + col0 + tid] = red[tid] + red[128 + tid];
}

// ---------------- binary-adjacency GEMM: A as raw bit-words in smem; fragments via ALU ----------------
// 32-K window pipeline.  DEGI=1: dinv = rsqrt(int deg).  grid (M/128, K/Kchunk, 2), 2 CTAs/SM.
template<int DEGI>
__global__ void __launch_bounds__(256, 2) k_mma_bin(
    const unsigned* __restrict__ bits, int nw,
    const float* __restrict__ H0, const float* __restrict__ H1, int ldh,
    const float* __restrict__ dinv,
    float* __restrict__ P, int M, int Kchunk, int nsl)
{
    __shared__ unsigned sB[2][32][136];
    __shared__ unsigned sAw[2][128];
    const float* H = blockIdx.z ? H1 : H0;
    const int row0 = blockIdx.x * 128;
    const int k0 = blockIdx.y * Kchunk;
    float* Pout = P + (size_t)(blockIdx.z * nsl + blockIdx.y) * ((size_t)M * 128);
    const int tid = threadIdx.x, lane = tid & 31, w = tid >> 5;
    const int wm = w >> 2, wn = w & 3, grp = lane >> 2, qid = lane & 3;
    const unsigned ONE = 0x3f800000u;

    float acc[4][4][4];
#pragma unroll
    for (int t = 0; t < 4; t++)
#pragma unroll
        for (int u = 0; u < 4; u++)
#pragma unroll
            for (int v = 0; v < 4; v++) acc[t][u][v] = 0.f;

    const int bk = tid >> 4, bnb = (tid & 15) * 8;
    float rb[16];
    unsigned wreg;

    {
        float dv0 = DEGI ? rsqrtf((float)((const int*)dinv)[k0 + bk])      : dinv[k0 + bk];
        float dv1 = DEGI ? rsqrtf((float)((const int*)dinv)[k0 + bk + 16]) : dinv[k0 + bk + 16];
        const float* b0p = H + (size_t)(k0 + bk) * ldh + bnb;
        const float* b1p = H + (size_t)(k0 + bk + 16) * ldh + bnb;
        float4 a0 = *(const float4*)b0p, a1 = *(const float4*)(b0p + 4);
        float4 c0 = *(const float4*)b1p, c1 = *(const float4*)(b1p + 4);
        rb[0]=a0.x*dv0; rb[1]=a0.y*dv0; rb[2]=a0.z*dv0; rb[3]=a0.w*dv0;
        rb[4]=a1.x*dv0; rb[5]=a1.y*dv0; rb[6]=a1.z*dv0; rb[7]=a1.w*dv0;
        rb[8]=c0.x*dv1; rb[9]=c0.y*dv1; rb[10]=c0.z*dv1; rb[11]=c0.w*dv1;
        rb[12]=c1.x*dv1; rb[13]=c1.y*dv1; rb[14]=c1.z*dv1; rb[15]=c1.w*dv1;
        if (tid < 128) wreg = bits[(size_t)(row0 + tid) * nw + (k0 >> 5)];
    }
#pragma unroll
    for (int i = 0; i < 8; i++) sB[0][bk][bnb + i] = f2tf(rb[i]);
#pragma unroll
    for (int i = 0; i < 8; i++) sB[0][bk + 16][bnb + i] = f2tf(rb[8 + i]);
    if (tid < 128) sAw[0][tid] = wreg;
    __syncthreads();

    const int nWin = Kchunk / 32;
    for (int win = 0; win < nWin; ++win) {
        const int cur = win & 1;
        const bool more = (win + 1) < nWin;
        if (more) {
            int kt = k0 + (win + 1) * 32;
            float dv0 = DEGI ? rsqrtf((float)((const int*)dinv)[kt + bk])      : dinv[kt + bk];
            float dv1 = DEGI ? rsqrtf((float)((const int*)dinv)[kt + bk + 16]) : dinv[kt + bk + 16];
            const float* b0p = H + (size_t)(kt + bk) * ldh + bnb;
            const float* b1p = H + (size_t)(kt + bk + 16) * ldh + bnb;
            float4 a0 = *(const float4*)b0p, a1 = *(const float4*)(b0p + 4);
            float4 c0 = *(const float4*)b1p, c1 = *(const float4*)(b1p + 4);
            rb[0]=a0.x*dv0; rb[1]=a0.y*dv0; rb[2]=a0.z*dv0; rb[3]=a0.w*dv0;
            rb[4]=a1.x*dv0; rb[5]=a1.y*dv0; rb[6]=a1.z*dv0; rb[7]=a1.w*dv0;
            rb[8]=c0.x*dv1; rb[9]=c0.y*dv1; rb[10]=c0.z*dv1; rb[11]=c0.w*dv1;
            rb[12]=c1.x*dv1; rb[13]=c1.y*dv1; rb[14]=c1.z*dv1; rb[15]=c1.w*dv1;
            if (tid < 128) wreg = bits[(size_t)(row0 + tid) * nw + ((kt) >> 5)];
        }
        unsigned w8[8];
#pragma unroll
        for (int t = 0; t < 4; t++) {
            w8[2 * t]     = sAw[cur][wm * 64 + t * 16 + grp];
            w8[2 * t + 1] = sAw[cur][wm * 64 + t * 16 + 8 + grp];
        }
#pragma unroll
        for (int s = 0; s < 2; s++) {
#pragma unroll
            for (int kk = 0; kk < 16; kk += 8) {
                const int sh = s * 16 + kk + qid;
                unsigned ah[4][4], bh[4][2];
#pragma unroll
                for (int t = 0; t < 4; t++) {
                    unsigned s0 = w8[2 * t] >> sh, s1 = w8[2 * t + 1] >> sh;
                    ah[t][0] = (s0 & 1u)  ? ONE : 0u;
                    ah[t][1] = (s1 & 1u)  ? ONE : 0u;
                    ah[t][2] = (s0 & 16u) ? ONE : 0u;
                    ah[t][3] = (s1 & 16u) ? ONE : 0u;
                }
#pragma unroll
                for (int u = 0; u < 4; u++) {
                    int c = wn * 32 + u * 8 + grp;
                    bh[u][0] = sB[cur][s * 16 + kk + qid][c];
                    bh[u][1] = sB[cur][s * 16 + kk + qid + 4][c];
                }
#pragma unroll
                for (int t = 0; t < 4; t++)
#pragma unroll
                    for (int u = 0; u < 4; u++)
                        mma8(acc[t][u], ah[t][0],ah[t][1],ah[t][2],ah[t][3], bh[u][0],bh[u][1]);
            }
        }
        if (more) {
#pragma unroll
            for (int i = 0; i < 8; i++) sB[cur ^ 1][bk][bnb + i] = f2tf(rb[i]);
#pragma unroll
            for (int i = 0; i < 8; i++) sB[cur ^ 1][bk + 16][bnb + i] = f2tf(rb[8 + i]);
            if (tid < 128) sAw[cur ^ 1][tid] = wreg;
        }
        __syncthreads();
    }
#pragma unroll
    for (int t = 0; t < 4; t++) {
        int r = row0 + wm * 64 + t * 16 + grp;
#pragma unroll
        for (int u = 0; u < 4; u++) {
            int c = wn * 32 + u * 8 + qid * 2;
            *(float2*)(Pout + (size_t)r * 128 + c)       = make_float2(acc[t][u][0], acc[t][u][1]);
            *(float2*)(Pout + (size_t)(r + 8) * 128 + c) = make_float2(acc[t][u][2], acc[t][u][3]);
        }
    }
}

// ---------------- reduce partials + bias + l2norm (+optional concat copy, +optional scores) ----------------
// grid (M/4, 1, 2), block 512 (4 rows x 128)
__global__ void k_red_l2(const float* __restrict__ P, int nsl, int cnt,
                         const float* __restrict__ bias,
                         float* __restrict__ O0, float* __restrict__ O1,
                         float* __restrict__ C0, float* __restrict__ C1, int cld,
                         const float* __restrict__ Wp, const float* __restrict__ bp)
{
    int z = blockIdx.z, t = threadIdx.x;
    int rloc = t >> 7, c = t & 127;
    int r = blockIdx.x * 4 + rloc;
    const float* Pz = P + (size_t)z * nsl * cnt;
    float s = bias[c];
    for (int k = 0; k < nsl; k++) s += Pz[(size_t)k * cnt + r * 128 + c];
    float q = s * s;
    for (int o = 16; o; o >>= 1) q += __shfl_xor_sync(~0u, q, o);
    __shared__ float ws[16];
    if ((t & 31) == 0) ws[t >> 5] = q;
    __syncthreads();
    float tot = ws[rloc * 4] + ws[rloc * 4 + 1] + ws[rloc * 4 + 2] + ws[rloc * 4 + 3];
    float v = s * rsqrtf(tot);
    float* O = z ? O1 : O0;
    O[(size_t)r * 128 + c] = v;
    if (C0) { float* C = z ? C1 : C0; C[(size_t)r * cld + c] = v; }
    if (Wp && z == 0) {
        float q2 = v * Wp[c];
        for (int o = 16; o; o >>= 1) q2 += __shfl_xor_sync(~0u, q2, o);
        __syncthreads();
        if ((t & 31) == 0) ws[t >> 5] = q2;
        __syncthreads();
        if (c == 0) {
            float sum = ws[rloc * 4] + ws[rloc * 4 + 1] + ws[rloc * 4 + 2] + ws[rloc * 4 + 3];
            g_scores[r] = 1.f / (1.f + __expf(-(sum + bp[0])));
        }
    }
}

// ---------------- reduce partials, float4, D^-1/2 row scale, write into concat at offset ----------------
// grid (cnt/1024, 1, 2), block 256.  DEGI=1: dinv from int degrees.
template<int DEGI>
__global__ void k_reduce_s4(const float* __restrict__ P, int nsl, int cnt,
                            float* __restrict__ O0, float* __restrict__ O1, int oldd, int ooff,
                            const float* __restrict__ dinv)
{
    int z = blockIdx.z;
    float* O = z ? O1 : O0;
    const float* Pz = P + (size_t)z * nsl * cnt;
    int e = (blockIdx.x * 256 + threadIdx.x) * 4;
    float4 s = make_float4(0.f, 0.f, 0.f, 0.f);
    for (int k = 0; k < nsl; k++) {
        float4 v = *(const float4*)(Pz + (size_t)k * cnt + e);
        s.x += v.x; s.y += v.y; s.z += v.z; s.w += v.w;
    }
    int r = e >> 7, c = e & 127;
    float d = DEGI ? rsqrtf((float)((const int*)dinv)[r]) : dinv[r];
    *(float4*)(O + (size_t)r * oldd + ooff + c) = make_float4(d * s.x, d * s.y, d * s.z, d * s.w);
}

// ---------------- top-1024 selection: grid-parallel rank select on packed 64-bit keys ----------------
// grid (16), block 128.  rank(e) = #{keys > key_e}; out[rank] = e (exact bitonic-descending order).
__global__ void k_pool1()
{
    __shared__ unsigned long long sk[2048];
    int t = threadIdx.x;
    for (int j = t; j < 2048; j += 128)
        sk[j] = ((unsigned long long)__float_as_uint(g_scores[j]) << 32) | (unsigned)(2047 - j);
    __syncthreads();
    int e = blockIdx.x * 128 + t;
    unsigned long long ke = sk[e];
    int cnt = 0;
#pragma unroll 8
    for (int j = 0; j < 2048; j++)
        cnt += (sk[j] > ke) ? 1 : 0;
    if (cnt < KP) {
        g_vals[cnt] = __uint_as_float((unsigned)(ke >> 32));
        g_idx[cnt] = 2047 - (int)(unsigned)(ke & 0xFFFFFFFFull);
    }
}

// ---------------- pooled 2-hop bits + dinvp + gather (merged), one pooled row per block ----------------
__global__ void k_pool2()
{
    __shared__ unsigned sbi[NW];
    __shared__ int ws[8];
    int i = blockIdx.x, t = threadIdx.x;
    int ii = g_idx[i];
    const unsigned* bi = g_bits + (size_t)ii * NW;
    if (t < NW) sbi[t] = bi[t];
    __syncthreads();
    int cnt = 0;
    for (int jb = 0; jb < KP; jb += 256) {
        int j = jb + t;
        const unsigned* bj = g_bits + (size_t)g_idx[j] * NW;
        bool c = false;
        for (int w = 0; w < NW && !c; w++) c = (sbi[w] & bj[w]) != 0u;
        unsigned word = __ballot_sync(~0u, c);
        cnt += c ? 1 : 0;
        if ((t & 31) == 0) g_bitsp[i * NWP + (j >> 5)] = word;
    }
    for (int o = 16; o; o >>= 1) cnt += __shfl_xor_sync(~0u, cnt, o);
    if ((t & 31) == 0) ws[t >> 5] = cnt;
    float vl = g_vals[i];
    int z = t >> 7, c = t & 127;
    g_catp[z][(size_t)i * 256 + c] = g_fg[z][(size_t)ii * 128 + c] * vl;
    __syncthreads();
    if (t == 0) {
        int s = 0;
        for (int k = 0; k < 8; k++) s += ws[k];
        g_dinvp[i] = rsqrtf((float)s);
    }
}

// ---------------- final: NCE combine for both stages + scalar ----------------
__global__ void k_final(float* __restrict__ out)
{
    int t = threadIdx.x;   // 1024 threads
    float sg = 0.f, sp = 0.f;
    for (int i = t; i < NN; i += 1024) {
        float s1 = 0.f, s2 = 0.f;
        for (int k = 0; k < 16; k++) { s1 += g_rp[k * NN + i]; s2 += g_cp[k * NN + i]; }
        sg += 2.f * INVT + __logf(s1) + __logf(s2) - 2.f * g_diag[i] * INVT;
    }
    {
        int i = t;
        float s1 = 0.f, s2 = 0.f;
        for (int k = 0; k < 8; k++) { s1 += g_rp2[k * KP + i]; s2 += g_cp2[k * KP + i]; }
        sp += 2.f * INVT + __logf(s1) + __logf(s2) - 2.f * g_diagp[i] * INVT;
    }
    for (int o = 16; o; o >>= 1) {
        sg += __shfl_xor_sync(~0u, sg, o);
        sp += __shfl_xor_sync(~0u, sp, o);
    }
    __shared__ float wg[32], wp[32];
    if ((t & 31) == 0) { wg[t >> 5] = sg; wp[t >> 5] = sp; }
    __syncthreads();
    if (t == 0) {
        float a = 0.f, b = 0.f;
        for (int i = 0; i < 32; i++) { a += wg[i]; b += wp[i]; }
        out[0] = a * (1.f / NN) + b * (1.f / KP);
    }
}

// ---------------- host ----------------
extern "C" void kernel_launch(void* const* d_in, const int* in_sizes, int n_in,
                              void* d_out, int out_size)
{
    (void)in_sizes; (void)n_in; (void)out_size;
    const float* fs    = (const float*)d_in[0];
    const float* ft    = (const float*)d_in[1];
    const float* We    = (const float*)d_in[2];
    const float* be    = (const float*)d_in[3];
    const float* Wg    = (const float*)d_in[4];
    const float* bg    = (const float*)d_in[5];
    const float* Wpool = (const float*)d_in[6];
    const float* bpool = (const float*)d_in[7];
    const float* Wgp   = (const float*)d_in[8];
    const float* bgp   = (const float*)d_in[9];

    void* p;
    cudaGetSymbolAddress(&p, g_fet);   float* FET  = (float*)p;
    cudaGetSymbolAddress(&p, g_fes);   float* FES  = (float*)p;
    cudaGetSymbolAddress(&p, g_bits);  unsigned* BITS  = (unsigned*)p;
    cudaGetSymbolAddress(&p, g_bitsp); unsigned* BITSP = (unsigned*)p;
    cudaGetSymbolAddress(&p, g_deg);   int*   DEG   = (int*)p;
    cudaGetSymbolAddress(&p, g_dinvp); float* DINVP = (float*)p;
    cudaGetSymbolAddress(&p, g_fg);    float* FG   = (float*)p;
    cudaGetSymbolAddress(&p, g_fp);    float* FP   = (float*)p;
    cudaGetSymbolAddress(&p, g_cat);   float* CAT  = (float*)p;
    cudaGetSymbolAddress(&p, g_catp);  float* CATP = (float*)p;
    cudaGetSymbolAddress(&p, g_part);  float* PART = (float*)p;
    cudaGetSymbolAddress(&p, g_rp);    float* RP   = (float*)p;
    cudaGetSymbolAddress(&p, g_cp);    float* CP   = (float*)p;
    cudaGetSymbolAddress(&p, g_rp2);   float* RP2  = (float*)p;
    cudaGetSymbolAddress(&p, g_cp2);   float* CP2  = (float*)p;
    cudaGetSymbolAddress(&p, g_diag);  float* DG1  = (float*)p;
    cudaGetSymbolAddress(&p, g_diagp); float* DG2  = (float*)p;

    const int ND = NN * DD;    // 262144
    const int KD = KP * DD;    // 131072
    const int CATLD = 384, CATPLD = 256;

    cudaStream_t sB;
    cudaEvent_t evF, evJ;
    cudaStreamCreateWithFlags(&sB, cudaStreamNonBlocking);
    cudaEventCreateWithFlags(&evF, cudaEventDisableTiming);
    cudaEventCreateWithFlags(&evJ, cudaEventDisableTiming);

    // 0) zero integer degrees (ordered before adjacency atomics on stream 0)
    cudaMemsetAsync(DEG, 0, NN * sizeof(int), 0);

    // 1) embed: f = l2norm(x @ We + be); z=0 teacher(ft), z=1 student(fs)
    k_mma_nn<<<dim3(16, 8, 2), 256>>>(ft, fs, CD, We, PART, NN, 64, 8);
    k_red_l2<<<dim3(NN / 4, 1, 2), 512>>>(PART, 8, ND, be, FET, FES, CAT, CAT + NN * CATLD, CATLD, (float*)0, (float*)0);

    // 2) adjacency bits from teacher gram (symmetric) + integer degrees via atomics
    k_mma_nt_adj<<<136, 256>>>(FET);

    // 3) TAGConv k=2 via binary MMA (dinv = rsqrt(deg) fused into B loader)
    k_mma_bin<1><<<dim3(16, 8, 2), 256>>>(BITS, NW, FET, FES, 128, (const float*)DEG, PART, NN, 256, 8);
    k_reduce_s4<1><<<dim3(ND / 1024, 1, 2), 256>>>(PART, 8, ND, CAT, CAT + NN * CATLD, CATLD, 128, (const float*)DEG);
    k_mma_bin<1><<<dim3(16, 8, 2), 256>>>(BITS, NW, CAT + 128, CAT + NN * CATLD + 128, CATLD, (const float*)DEG, PART, NN, 256, 8);
    k_reduce_s4<1><<<dim3(ND / 1024, 1, 2), 256>>>(PART, 8, ND, CAT, CAT + NN * CATLD, CATLD, 256, (const float*)DEG);

    // 4) concat GEMM (K=384, Kchunk=96) + bias + l2norm -> FG, + fused pooling scores (z=0)
    k_mma_nn<<<dim3(16, 4, 2), 256>>>(CAT, CAT + NN * CATLD, CATLD, Wg, PART, NN, 96, 4);
    k_red_l2<<<dim3(NN / 4, 1, 2), 512>>>(PART, 4, ND, bg, FG, FG + ND, (float*)0, (float*)0, 0, Wpool, bpool);

    // 5) stage-1 NCE on side stream, overlapped with the pooling chain
    cudaEventRecord(evF, 0);
    cudaStreamWaitEvent(sB, evF, 0);
    k_mma_nt_nce<<<dim3(16, 16), 256, 0, sB>>>(FG, FG + ND, NN, RP, CP, DG1);
    cudaEventRecord(evJ, sB);

    // 6) pooling: grid-parallel rank selection, then bits+dinvp+gather merged
    k_pool1<<<16, 128>>>();
    k_pool2<<<KP, 256>>>();

    // 7) pooled TAGConv k=1 (dinvp fused into loader)
    k_mma_bin<0><<<dim3(8, 8, 2), 256>>>(BITSP, NWP, CATP, CATP + KP * CATPLD, CATPLD, DINVP, PART, KP, 128, 8);
    k_reduce_s4<0><<<dim3(KD / 1024, 1, 2), 256>>>(PART, 8, KD, CATP, CATP + KP * CATPLD, CATPLD, 128, DINVP);
    k_mma_nn<<<dim3(8, 4, 2), 256>>>(CATP, CATP + KP * CATPLD, CATPLD, Wgp, PART, KP, 64, 4);
    k_red_l2<<<dim3(KP / 4, 1, 2), 512>>>(PART, 4, KD, bgp, FP, FP + KD, (float*)0, (float*)0, 0, (float*)0, (float*)0);

    // 8) pooled NCE
    k_mma_nt_nce<<<dim3(8, 8), 256>>>(FP, FP + KD, KP, RP2, CP2, DG2);

    // 9) join + NCE combine (both stages) + final scalar
    cudaStreamWaitEvent(0, evJ, 0);
    k_final<<<1, 1024>>>((float*)d_out);
}

// round 13
// speedup vs baseline: 2.2017x; 2.2017x over previous
#include <cuda_runtime.h>
#include <math.h>

// ---------------- problem constants ----------------
#define NN 2048
#define CD 512
#define DD 128
#define KP 1024
#define NW 64            // 2048 bits / 32
#define NWP 32           // 1024 bits / 32
#define INVT 14.285714285714286f

// ---------------- device scratch ----------------
__device__ __align__(16) float g_fet[NN*DD];
__device__ __align__(16) float g_fes[NN*DD];
__device__ unsigned g_bits[NN*NW];
__device__ unsigned g_bitsp[KP*NWP];
__device__ int   g_deg[NN];
__device__ float g_dinvp[KP];
__device__ __align__(16) float g_fg[2][NN*DD];     // [0]=teacher,[1]=student
__device__ __align__(16) float g_fp[2][KP*DD];
__device__ __align__(16) float g_cat[2][NN*384];   // concat [h0|h1|h2]
__device__ __align__(16) float g_catp[2][KP*256];  // pooled concat [newh|h1p]
__device__ float g_scores[NN];
__device__ int   g_idx[KP];
__device__ float g_vals[KP];
__device__ __align__(16) float g_part[16][NN*DD];  // split-K partials
__device__ float g_rp[16*NN], g_cp[16*NN], g_diag[NN];
__device__ float g_rp2[8*KP], g_cp2[8*KP], g_diagp[KP];

// ---------------- tf32 helpers ----------------
__device__ __forceinline__ unsigned f2tf(float x) {
    unsigned r; asm("cvt.rna.tf32.f32 %0, %1;" : "=r"(r) : "f"(x)); return r;
}
__device__ __forceinline__ void mma8(float c[4], unsigned a0, unsigned a1, unsigned a2, unsigned a3,
                                     unsigned b0, unsigned b1) {
    asm volatile("mma.sync.aligned.m16n8k8.row.col.f32.tf32.tf32.f32 "
                 "{%0,%1,%2,%3}, {%4,%5,%6,%7}, {%8,%9}, {%0,%1,%2,%3};\n"
                 : "+f"(c[0]), "+f"(c[1]), "+f"(c[2]), "+f"(c[3])
                 : "r"(a0), "r"(a1), "r"(a2), "r"(a3), "r"(b0), "r"(b1));
}

// ---- MMA over one 16-K stage, 3-pass tf32 split (fp32-accurate), raw-float smem ----
__device__ __forceinline__ void mma_tile_split(
    float acc[4][4][4], const float (*__restrict__ sa)[132], const float (*__restrict__ sb)[136],
    int wm, int wn, int grp, int qid)
{
#pragma unroll
    for (int kk = 0; kk < 16; kk += 8) {
        float araw[4][4], braw[4][2];
        unsigned ah[4][4], bh[4][2];
#pragma unroll
        for (int t = 0; t < 4; t++) {
            int r = wm*64 + t*16 + grp;
            araw[t][0] = sa[kk+qid][r];   araw[t][1] = sa[kk+qid][r+8];
            araw[t][2] = sa[kk+qid+4][r]; araw[t][3] = sa[kk+qid+4][r+8];
#pragma unroll
            for (int j = 0; j < 4; j++) ah[t][j] = f2tf(araw[t][j]);
        }
#pragma unroll
        for (int u = 0; u < 4; u++) {
            int c = wn*32 + u*8 + grp;
            braw[u][0] = sb[kk+qid][c]; braw[u][1] = sb[kk+qid+4][c];
            bh[u][0] = f2tf(braw[u][0]); bh[u][1] = f2tf(braw[u][1]);
        }
#pragma unroll
        for (int t = 0; t < 4; t++)
#pragma unroll
            for (int u = 0; u < 4; u++)
                mma8(acc[t][u], ah[t][0],ah[t][1],ah[t][2],ah[t][3], bh[u][0],bh[u][1]);
        {
            unsigned bl[4][2];
#pragma unroll
            for (int u = 0; u < 4; u++) {
                bl[u][0] = f2tf(braw[u][0] - __uint_as_float(bh[u][0]));
                bl[u][1] = f2tf(braw[u][1] - __uint_as_float(bh[u][1]));
            }
#pragma unroll
            for (int t = 0; t < 4; t++)
#pragma unroll
                for (int u = 0; u < 4; u++)
                    mma8(acc[t][u], ah[t][0],ah[t][1],ah[t][2],ah[t][3], bl[u][0],bl[u][1]);
        }
        {
            unsigned al[4][4];
#pragma unroll
            for (int t = 0; t < 4; t++)
#pragma unroll
                for (int j = 0; j < 4; j++)
                    al[t][j] = f2tf(araw[t][j] - __uint_as_float(ah[t][j]));
#pragma unroll
            for (int t = 0; t < 4; t++)
#pragma unroll
                for (int u = 0; u < 4; u++)
                    mma8(acc[t][u], al[t][0],al[t][1],al[t][2],al[t][3], bh[u][0],bh[u][1]);
        }
    }
}

// ---- MMA over one 16-K stage, single-pass, pre-converted tf32 smem ----
__device__ __forceinline__ void mma_tile_1p_u(
    float acc[4][4][4], const unsigned (*__restrict__ sa)[132], const unsigned (*__restrict__ sb)[136],
    int wm, int wn, int grp, int qid)
{
#pragma unroll
    for (int kk = 0; kk < 16; kk += 8) {
        unsigned ah[4][4], bh[4][2];
#pragma unroll
        for (int t = 0; t < 4; t++) {
            int r = wm*64 + t*16 + grp;
            ah[t][0] = sa[kk+qid][r];   ah[t][1] = sa[kk+qid][r+8];
            ah[t][2] = sa[kk+qid+4][r]; ah[t][3] = sa[kk+qid+4][r+8];
        }
#pragma unroll
        for (int u = 0; u < 4; u++) {
            int c = wn*32 + u*8 + grp;
            bh[u][0] = sb[kk+qid][c]; bh[u][1] = sb[kk+qid+4][c];
        }
#pragma unroll
        for (int t = 0; t < 4; t++)
#pragma unroll
            for (int u = 0; u < 4; u++)
                mma8(acc[t][u], ah[t][0],ah[t][1],ah[t][2],ah[t][3], bh[u][0],bh[u][1]);
    }
}

// ---------------- NN GEMM, split-tf32, double-buffered: C[M,128]=A[M,K]@B[K,128] ----------------
// grid (M/128, K/Kchunk, 2), block 256
__global__ void __launch_bounds__(256) k_mma_nn(
    const float* __restrict__ A0, const float* __restrict__ A1, int lda,
    const float* __restrict__ B,
    float* __restrict__ P, int M, int Kchunk, int nsl)
{
    __shared__ float sA[2][16][132];
    __shared__ float sB[2][16][136];
    const float* A = blockIdx.z ? A1 : A0;
    const int row0 = blockIdx.x * 128;
    const int k0 = blockIdx.y * Kchunk;
    float* Pout = P + (size_t)(blockIdx.z * nsl + blockIdx.y) * ((size_t)M * 128);
    const int tid = threadIdx.x, lane = tid & 31, w = tid >> 5;
    const int wm = w >> 2, wn = w & 3, grp = lane >> 2, qid = lane & 3;

    float acc[4][4][4];
#pragma unroll
    for (int t = 0; t < 4; t++)
#pragma unroll
        for (int u = 0; u < 4; u++)
#pragma unroll
            for (int v = 0; v < 4; v++) acc[t][u][v] = 0.f;

    const int ar = tid >> 1, akb = (tid & 1) * 8;
    const int bk = tid >> 4, bnb = (tid & 15) * 8;
    float ra[8], rb[8];

    {
        const float* as_ = A + (size_t)(row0 + ar) * lda + k0 + akb;
        float4 a0 = *(const float4*)as_, a1 = *(const float4*)(as_ + 4);
        ra[0]=a0.x; ra[1]=a0.y; ra[2]=a0.z; ra[3]=a0.w; ra[4]=a1.x; ra[5]=a1.y; ra[6]=a1.z; ra[7]=a1.w;
        const float* bs_ = B + (size_t)(k0 + bk) * 128 + bnb;
        float4 b0 = *(const float4*)bs_, b1 = *(const float4*)(bs_ + 4);
        rb[0]=b0.x; rb[1]=b0.y; rb[2]=b0.z; rb[3]=b0.w; rb[4]=b1.x; rb[5]=b1.y; rb[6]=b1.z; rb[7]=b1.w;
    }
    const int nIter = Kchunk / 16;
#pragma unroll
    for (int i = 0; i < 8; i++) sA[0][akb + i][ar] = ra[i];
#pragma unroll
    for (int i = 0; i < 8; i++) sB[0][bk][bnb + i] = rb[i];
    __syncthreads();

    for (int it = 0; it < nIter; ++it) {
        const int cur = it & 1;
        const bool more = (it + 1) < nIter;
        if (more) {
            int kt = k0 + (it + 1) * 16;
            const float* as_ = A + (size_t)(row0 + ar) * lda + kt + akb;
            float4 a0 = *(const float4*)as_, a1 = *(const float4*)(as_ + 4);
            ra[0]=a0.x; ra[1]=a0.y; ra[2]=a0.z; ra[3]=a0.w; ra[4]=a1.x; ra[5]=a1.y; ra[6]=a1.z; ra[7]=a1.w;
            const float* bs_ = B + (size_t)(kt + bk) * 128 + bnb;
            float4 b0 = *(const float4*)bs_, b1 = *(const float4*)(bs_ + 4);
            rb[0]=b0.x; rb[1]=b0.y; rb[2]=b0.z; rb[3]=b0.w; rb[4]=b1.x; rb[5]=b1.y; rb[6]=b1.z; rb[7]=b1.w;
        }
        mma_tile_split(acc, sA[cur], sB[cur], wm, wn, grp, qid);
        if (more) {
#pragma unroll
            for (int i = 0; i < 8; i++) sA[cur ^ 1][akb + i][ar] = ra[i];
#pragma unroll
            for (int i = 0; i < 8; i++) sB[cur ^ 1][bk][bnb + i] = rb[i];
        }
        __syncthreads();
    }
#pragma unroll
    for (int t = 0; t < 4; t++) {
        int r = row0 + wm * 64 + t * 16 + grp;
#pragma unroll
        for (int u = 0; u < 4; u++) {
            int c = wn * 32 + u * 8 + qid * 2;
            *(float2*)(Pout + (size_t)r * 128 + c)       = make_float2(acc[t][u][0], acc[t][u][1]);
            *(float2*)(Pout + (size_t)(r + 8) * 128 + c) = make_float2(acc[t][u][2], acc[t][u][3]);
        }
    }
}

// ---------------- adjacency gram (SYMMETRIC): bits = (F F^T > 0) + integer degree atomics ----------------
// grid (136), block 256.  Off-diagonal tiles also emit the transposed bit-block.
__global__ void __launch_bounds__(256) k_mma_nt_adj(const float* __restrict__ F)
{
    __shared__ float sA[2][16][132];
    __shared__ float sB[2][16][136];
    __shared__ unsigned srow[128][5];
    int i = blockIdx.x;
    int by = (int)((sqrtf(8.f * i + 1.f) - 1.f) * 0.5f);
    while ((by + 1) * (by + 2) / 2 <= i) by++;
    while (by * (by + 1) / 2 > i) by--;
    int bx = i - by * (by + 1) / 2;
    const int row0 = bx * 128, col0 = by * 128;
    const int tid = threadIdx.x, lane = tid & 31, w = tid >> 5;
    const int wm = w >> 2, wn = w & 3, grp = lane >> 2, qid = lane & 3;

    float acc[4][4][4];
#pragma unroll
    for (int t = 0; t < 4; t++)
#pragma unroll
        for (int u = 0; u < 4; u++)
#pragma unroll
            for (int v = 0; v < 4; v++) acc[t][u][v] = 0.f;

    const int fr = tid >> 1, fkb = (tid & 1) * 8;
    float ra[8], rb[8];
    {
        const float* as_ = F + (size_t)(row0 + fr) * 128 + fkb;
        float4 a0 = *(const float4*)as_, a1 = *(const float4*)(as_ + 4);
        ra[0]=a0.x; ra[1]=a0.y; ra[2]=a0.z; ra[3]=a0.w; ra[4]=a1.x; ra[5]=a1.y; ra[6]=a1.z; ra[7]=a1.w;
        const float* bs_ = F + (size_t)(col0 + fr) * 128 + fkb;
        float4 b0 = *(const float4*)bs_, b1 = *(const float4*)(bs_ + 4);
        rb[0]=b0.x; rb[1]=b0.y; rb[2]=b0.z; rb[3]=b0.w; rb[4]=b1.x; rb[5]=b1.y; rb[6]=b1.z; rb[7]=b1.w;
    }
#pragma unroll
    for (int i2 = 0; i2 < 8; i2++) sA[0][fkb + i2][fr] = ra[i2];
#pragma unroll
    for (int i2 = 0; i2 < 8; i2++) sB[0][fkb + i2][fr] = rb[i2];
    __syncthreads();

    for (int it = 0; it < 8; ++it) {
        const int cur = it & 1;
        const bool more = it < 7;
        if (more) {
            int kt = (it + 1) * 16;
            const float* as_ = F + (size_t)(row0 + fr) * 128 + kt + fkb;
            float4 a0 = *(const float4*)as_, a1 = *(const float4*)(as_ + 4);
            ra[0]=a0.x; ra[1]=a0.y; ra[2]=a0.z; ra[3]=a0.w; ra[4]=a1.x; ra[5]=a1.y; ra[6]=a1.z; ra[7]=a1.w;
            const float* bs_ = F + (size_t)(col0 + fr) * 128 + kt + fkb;
            float4 b0 = *(const float4*)bs_, b1 = *(const float4*)(bs_ + 4);
            rb[0]=b0.x; rb[1]=b0.y; rb[2]=b0.z; rb[3]=b0.w; rb[4]=b1.x; rb[5]=b1.y; rb[6]=b1.z; rb[7]=b1.w;
        }
        mma_tile_split(acc, sA[cur], sB[cur], wm, wn, grp, qid);
        if (more) {
#pragma unroll
            for (int i2 = 0; i2 < 8; i2++) sA[cur ^ 1][fkb + i2][fr] = ra[i2];
#pragma unroll
            for (int i2 = 0; i2 < 8; i2++) sB[cur ^ 1][fkb + i2][fr] = rb[i2];
        }
        __syncthreads();
    }
#pragma unroll
    for (int t = 0; t < 4; t++)
#pragma unroll
        for (int h = 0; h < 2; h++) {
            unsigned m = 0;
#pragma unroll
            for (int u = 0; u < 4; u++)
#pragma unroll
                for (int vv = 0; vv < 2; vv++)
                    if (acc[t][u][h * 2 + vv] > 0.f) m |= 1u << (u * 8 + qid * 2 + vv);
            m |= __shfl_xor_sync(~0u, m, 1);
            m |= __shfl_xor_sync(~0u, m, 2);
            if (qid == 0) {
                int rl = wm * 64 + t * 16 + h * 8 + grp;
                g_bits[(size_t)(row0 + rl) * NW + (col0 >> 5) + wn] = m;
                srow[rl][wn] = m;
                atomicAdd(&g_deg[row0 + rl], __popc(m));
            }
        }
    if (row0 != col0) {
        __syncthreads();
        for (int idx = tid; idx < 512; idx += 256) {
            int j = idx >> 2, wq = idx & 3;
            unsigned o = 0;
#pragma unroll
            for (int b = 0; b < 32; b++)
                o |= ((srow[wq * 32 + b][j >> 5] >> (j & 31)) & 1u) << b;
            g_bits[(size_t)(col0 + j) * NW + (row0 >> 5) + wq] = o;
            atomicAdd(&g_deg[col0 + j], __popc(o));
        }
    }
}

// ---------------- NCE gram: exp row/col partial sums + diag; pre-converted tf32 smem ----------------
// grid (n/128, n/128), block 256, 2 CTAs/SM
__global__ void __launch_bounds__(256, 2) k_mma_nt_nce(
    const float* __restrict__ F, const float* __restrict__ Gm, int n,
    float* __restrict__ RP, float* __restrict__ CP, float* __restrict__ diag)
{
    __shared__ unsigned sA[2][16][132];
    __shared__ unsigned sB[2][16][136];
    const int row0 = blockIdx.x * 128, col0 = blockIdx.y * 128;
    const int tid = threadIdx.x, lane = tid & 31, w = tid >> 5;
    const int wm = w >> 2, wn = w & 3, grp = lane >> 2, qid = lane & 3;

    float acc[4][4][4];
#pragma unroll
    for (int t = 0; t < 4; t++)
#pragma unroll
        for (int u = 0; u < 4; u++)
#pragma unroll
            for (int v = 0; v < 4; v++) acc[t][u][v] = 0.f;

    const int fr = tid >> 1, fkb = (tid & 1) * 8;
    float ra[8], rb[8];
    {
        const float* as_ = F + (size_t)(row0 + fr) * 128 + fkb;
        float4 a0 = *(const float4*)as_, a1 = *(const float4*)(as_ + 4);
        ra[0]=a0.x; ra[1]=a0.y; ra[2]=a0.z; ra[3]=a0.w; ra[4]=a1.x; ra[5]=a1.y; ra[6]=a1.z; ra[7]=a1.w;
        const float* bs_ = Gm + (size_t)(col0 + fr) * 128 + fkb;
        float4 b0 = *(const float4*)bs_, b1 = *(const float4*)(bs_ + 4);
        rb[0]=b0.x; rb[1]=b0.y; rb[2]=b0.z; rb[3]=b0.w; rb[4]=b1.x; rb[5]=b1.y; rb[6]=b1.z; rb[7]=b1.w;
    }
#pragma unroll
    for (int i = 0; i < 8; i++) sA[0][fkb + i][fr] = f2tf(ra[i]);
#pragma unroll
    for (int i = 0; i < 8; i++) sB[0][fkb + i][fr] = f2tf(rb[i]);
    __syncthreads();

    for (int it = 0; it < 8; ++it) {
        const int cur = it & 1;
        const bool more = it < 7;
        if (more) {
            int kt = (it + 1) * 16;
            const float* as_ = F + (size_t)(row0 + fr) * 128 + kt + fkb;
            float4 a0 = *(const float4*)as_, a1 = *(const float4*)(as_ + 4);
            ra[0]=a0.x; ra[1]=a0.y; ra[2]=a0.z; ra[3]=a0.w; ra[4]=a1.x; ra[5]=a1.y; ra[6]=a1.z; ra[7]=a1.w;
            const float* bs_ = Gm + (size_t)(col0 + fr) * 128 + kt + fkb;
            float4 b0 = *(const float4*)bs_, b1 = *(const float4*)(bs_ + 4);
            rb[0]=b0.x; rb[1]=b0.y; rb[2]=b0.z; rb[3]=b0.w; rb[4]=b1.x; rb[5]=b1.y; rb[6]=b1.z; rb[7]=b1.w;
        }
        mma_tile_1p_u(acc, sA[cur], sB[cur], wm, wn, grp, qid);
        if (more) {
#pragma unroll
            for (int i = 0; i < 8; i++) sA[cur ^ 1][fkb + i][fr] = f2tf(ra[i]);
#pragma unroll
            for (int i = 0; i < 8; i++) sB[cur ^ 1][fkb + i][fr] = f2tf(rb[i]);
        }
        __syncthreads();
    }

    if (blockIdx.x == blockIdx.y) {
#pragma unroll
        for (int t = 0; t < 4; t++)
#pragma unroll
            for (int u = 0; u < 4; u++)
#pragma unroll
                for (int v = 0; v < 4; v++) {
                    int r = wm * 64 + t * 16 + (v >> 1) * 8 + grp;
                    int c = wn * 32 + u * 8 + qid * 2 + (v & 1);
                    if (r == c) diag[row0 + r] = acc[t][u][v];
                }
    }
#pragma unroll
    for (int t = 0; t < 4; t++)
#pragma unroll
        for (int u = 0; u < 4; u++)
#pragma unroll
            for (int v = 0; v < 4; v++)
                acc[t][u][v] = __expf(acc[t][u][v] * INVT - INVT);

    float* red = (float*)sA;
#pragma unroll
    for (int t = 0; t < 4; t++)
#pragma unroll
        for (int h = 0; h < 2; h++) {
            float rs = 0.f;
#pragma unroll
            for (int u = 0; u < 4; u++)
#pragma unroll
                for (int vv = 0; vv < 2; vv++) rs += acc[t][u][h * 2 + vv];
            rs += __shfl_xor_sync(~0u, rs, 1);
            rs += __shfl_xor_sync(~0u, rs, 2);
            if (qid == 0) red[wn * 128 + wm * 64 + t * 16 + h * 8 + grp] = rs;
        }
    __syncthreads();
    if (tid < 128)
        RP[(size_t)blockIdx.y * n + row0 + tid] = red[tid] + red[128 + tid] + red[256 + tid] + red[384 + tid];
    __syncthreads();
#pragma unroll
    for (int u = 0; u < 4; u++)
#pragma unroll
        for (int vv = 0; vv < 2; vv++) {
            float cs = 0.f;
#pragma unroll
            for (int t = 0; t < 4; t++)
#pragma unroll
                for (int h = 0; h < 2; h++) cs += acc[t][u][h * 2 + vv];
            cs += __shfl_xor_sync(~0u, cs, 4);
            cs += __shfl_xor_sync(~0u, cs, 8);
            cs += __shfl_xor_sync(~0u, cs, 16);
            if (grp == 0) red[wm * 128 + wn * 32 + u * 8 + qid * 2 + vv] = cs;
        }
    __syncthreads();
    if (tid < 128)
        CP[(size_t)blockIdx.x * n + col0 + tid] = red[tid] + red[128 + tid];
}

// ---------------- binary-adjacency GEMM: A as raw bit-words in smem; fragments via ALU ----------------
// 32-K window pipeline.  DEGI=1: dinv = rsqrt(int deg).  grid (M/128, K/Kchunk, 2), 2 CTAs/SM.
template<int DEGI>
__global__ void __launch_bounds__(256, 2) k_mma_bin(
    const unsigned* __restrict__ bits, int nw,
    const float* __restrict__ H0, const float* __restrict__ H1, int ldh,
    const float* __restrict__ dinv,
    float* __restrict__ P, int M, int Kchunk, int nsl)
{
    __shared__ unsigned sB[2][32][136];
    __shared__ unsigned sAw[2][128];
    const float* H = blockIdx.z ? H1 : H0;
    const int row0 = blockIdx.x * 128;
    const int k0 = blockIdx.y * Kchunk;
    float* Pout = P + (size_t)(blockIdx.z * nsl + blockIdx.y) * ((size_t)M * 128);
    const int tid = threadIdx.x, lane = tid & 31, w = tid >> 5;
    const int wm = w >> 2, wn = w & 3, grp = lane >> 2, qid = lane & 3;
    const unsigned ONE = 0x3f800000u;

    float acc[4][4][4];
#pragma unroll
    for (int t = 0; t < 4; t++)
#pragma unroll
        for (int u = 0; u < 4; u++)
#pragma unroll
            for (int v = 0; v < 4; v++) acc[t][u][v] = 0.f;

    const int bk = tid >> 4, bnb = (tid & 15) * 8;
    float rb[16];
    unsigned wreg;

    {
        float dv0 = DEGI ? rsqrtf((float)((const int*)dinv)[k0 + bk])      : dinv[k0 + bk];
        float dv1 = DEGI ? rsqrtf((float)((const int*)dinv)[k0 + bk + 16]) : dinv[k0 + bk + 16];
        const float* b0p = H + (size_t)(k0 + bk) * ldh + bnb;
        const float* b1p = H + (size_t)(k0 + bk + 16) * ldh + bnb;
        float4 a0 = *(const float4*)b0p, a1 = *(const float4*)(b0p + 4);
        float4 c0 = *(const float4*)b1p, c1 = *(const float4*)(b1p + 4);
        rb[0]=a0.x*dv0; rb[1]=a0.y*dv0; rb[2]=a0.z*dv0; rb[3]=a0.w*dv0;
        rb[4]=a1.x*dv0; rb[5]=a1.y*dv0; rb[6]=a1.z*dv0; rb[7]=a1.w*dv0;
        rb[8]=c0.x*dv1; rb[9]=c0.y*dv1; rb[10]=c0.z*dv1; rb[11]=c0.w*dv1;
        rb[12]=c1.x*dv1; rb[13]=c1.y*dv1; rb[14]=c1.z*dv1; rb[15]=c1.w*dv1;
        if (tid < 128) wreg = bits[(size_t)(row0 + tid) * nw + (k0 >> 5)];
    }
#pragma unroll
    for (int i = 0; i < 8; i++) sB[0][bk][bnb + i] = f2tf(rb[i]);
#pragma unroll
    for (int i = 0; i < 8; i++) sB[0][bk + 16][bnb + i] = f2tf(rb[8 + i]);
    if (tid < 128) sAw[0][tid] = wreg;
    __syncthreads();

    const int nWin = Kchunk / 32;
    for (int win = 0; win < nWin; ++win) {
        const int cur = win & 1;
        const bool more = (win + 1) < nWin;
        if (more) {
            int kt = k0 + (win + 1) * 32;
            float dv0 = DEGI ? rsqrtf((float)((const int*)dinv)[kt + bk])      : dinv[kt + bk];
            float dv1 = DEGI ? rsqrtf((float)((const int*)dinv)[kt + bk + 16]) : dinv[kt + bk + 16];
            const float* b0p = H + (size_t)(kt + bk) * ldh + bnb;
            const float* b1p = H + (size_t)(kt + bk + 16) * ldh + bnb;
            float4 a0 = *(const float4*)b0p, a1 = *(const float4*)(b0p + 4);
            float4 c0 = *(const float4*)b1p, c1 = *(const float4*)(b1p + 4);
            rb[0]=a0.x*dv0; rb[1]=a0.y*dv0; rb[2]=a0.z*dv0; rb[3]=a0.w*dv0;
            rb[4]=a1.x*dv0; rb[5]=a1.y*dv0; rb[6]=a1.z*dv0; rb[7]=a1.w*dv0;
            rb[8]=c0.x*dv1; rb[9]=c0.y*dv1; rb[10]=c0.z*dv1; rb[11]=c0.w*dv1;
            rb[12]=c1.x*dv1; rb[13]=c1.y*dv1; rb[14]=c1.z*dv1; rb[15]=c1.w*dv1;
            if (tid < 128) wreg = bits[(size_t)(row0 + tid) * nw + ((kt) >> 5)];
        }
        unsigned w8[8];
#pragma unroll
        for (int t = 0; t < 4; t++) {
            w8[2 * t]     = sAw[cur][wm * 64 + t * 16 + grp];
            w8[2 * t + 1] = sAw[cur][wm * 64 + t * 16 + 8 + grp];
        }
#pragma unroll
        for (int s = 0; s < 2; s++) {
#pragma unroll
            for (int kk = 0; kk < 16; kk += 8) {
                const int sh = s * 16 + kk + qid;
                unsigned ah[4][4], bh[4][2];
#pragma unroll
                for (int t = 0; t < 4; t++) {
                    unsigned s0 = w8[2 * t] >> sh, s1 = w8[2 * t + 1] >> sh;
                    ah[t][0] = (s0 & 1u)  ? ONE : 0u;
                    ah[t][1] = (s1 & 1u)  ? ONE : 0u;
                    ah[t][2] = (s0 & 16u) ? ONE : 0u;
                    ah[t][3] = (s1 & 16u) ? ONE : 0u;
                }
#pragma unroll
                for (int u = 0; u < 4; u++) {
                    int c = wn * 32 + u * 8 + grp;
                    bh[u][0] = sB[cur][s * 16 + kk + qid][c];
                    bh[u][1] = sB[cur][s * 16 + kk + qid + 4][c];
                }
#pragma unroll
                for (int t = 0; t < 4; t++)
#pragma unroll
                    for (int u = 0; u < 4; u++)
                        mma8(acc[t][u], ah[t][0],ah[t][1],ah[t][2],ah[t][3], bh[u][0],bh[u][1]);
            }
        }
        if (more) {
#pragma unroll
            for (int i = 0; i < 8; i++) sB[cur ^ 1][bk][bnb + i] = f2tf(rb[i]);
#pragma unroll
            for (int i = 0; i < 8; i++) sB[cur ^ 1][bk + 16][bnb + i] = f2tf(rb[8 + i]);
            if (tid < 128) sAw[cur ^ 1][tid] = wreg;
        }
        __syncthreads();
    }
#pragma unroll
    for (int t = 0; t < 4; t++) {
        int r = row0 + wm * 64 + t * 16 + grp;
#pragma unroll
        for (int u = 0; u < 4; u++) {
            int c = wn * 32 + u * 8 + qid * 2;
            *(float2*)(Pout + (size_t)r * 128 + c)       = make_float2(acc[t][u][0], acc[t][u][1]);
            *(float2*)(Pout + (size_t)(r + 8) * 128 + c) = make_float2(acc[t][u][2], acc[t][u][3]);
        }
    }
}

// ---------------- reduce partials + bias + l2norm (+optional concat copy, +optional scores) ----------------
// grid (M/4, 1, 2), block 512 (4 rows x 128)
__global__ void k_red_l2(const float* __restrict__ P, int nsl, int cnt,
                         const float* __restrict__ bias,
                         float* __restrict__ O0, float* __restrict__ O1,
                         float* __restrict__ C0, float* __restrict__ C1, int cld,
                         const float* __restrict__ Wp, const float* __restrict__ bp)
{
    int z = blockIdx.z, t = threadIdx.x;
    int rloc = t >> 7, c = t & 127;
    int r = blockIdx.x * 4 + rloc;
    const float* Pz = P + (size_t)z * nsl * cnt;
    float s = bias[c];
    for (int k = 0; k < nsl; k++) s += Pz[(size_t)k * cnt + r * 128 + c];
    float q = s * s;
    for (int o = 16; o; o >>= 1) q += __shfl_xor_sync(~0u, q, o);
    __shared__ float ws[16];
    if ((t & 31) == 0) ws[t >> 5] = q;
    __syncthreads();
    float tot = ws[rloc * 4] + ws[rloc * 4 + 1] + ws[rloc * 4 + 2] + ws[rloc * 4 + 3];
    float v = s * rsqrtf(tot);
    float* O = z ? O1 : O0;
    O[(size_t)r * 128 + c] = v;
    if (C0) { float* C = z ? C1 : C0; C[(size_t)r * cld + c] = v; }
    if (Wp && z == 0) {
        float q2 = v * Wp[c];
        for (int o = 16; o; o >>= 1) q2 += __shfl_xor_sync(~0u, q2, o);
        __syncthreads();
        if ((t & 31) == 0) ws[t >> 5] = q2;
        __syncthreads();
        if (c == 0) {
            float sum = ws[rloc * 4] + ws[rloc * 4 + 1] + ws[rloc * 4 + 2] + ws[rloc * 4 + 3];
            g_scores[r] = 1.f / (1.f + __expf(-(sum + bp[0])));
        }
    }
}

// ---------------- reduce partials, float4, D^-1/2 row scale, write into concat at offset ----------------
// grid (cnt/1024, 1, 2), block 256.  DEGI=1: dinv from int degrees.
template<int DEGI>
__global__ void k_reduce_s4(const float* __restrict__ P, int nsl, int cnt,
                            float* __restrict__ O0, float* __restrict__ O1, int oldd, int ooff,
                            const float* __restrict__ dinv)
{
    int z = blockIdx.z;
    float* O = z ? O1 : O0;
    const float* Pz = P + (size_t)z * nsl * cnt;
    int e = (blockIdx.x * 256 + threadIdx.x) * 4;
    float4 s = make_float4(0.f, 0.f, 0.f, 0.f);
    for (int k = 0; k < nsl; k++) {
        float4 v = *(const float4*)(Pz + (size_t)k * cnt + e);
        s.x += v.x; s.y += v.y; s.z += v.z; s.w += v.w;
    }
    int r = e >> 7, c = e & 127;
    float d = DEGI ? rsqrtf((float)((const int*)dinv)[r]) : dinv[r];
    *(float4*)(O + (size_t)r * oldd + ooff + c) = make_float4(d * s.x, d * s.y, d * s.z, d * s.w);
}

// ---------------- top-1024 selection: bitonic on packed 64-bit keys ----------------
__global__ void k_pool1()
{
    __shared__ unsigned long long sk[2048];
    int t = threadIdx.x;
    for (int r = t; r < 2048; r += 1024)
        sk[r] = ((unsigned long long)__float_as_uint(g_scores[r]) << 32) | (unsigned)(2047 - r);
    __syncthreads();
    for (int k = 2; k <= 2048; k <<= 1)
        for (int j = k >> 1; j > 0; j >>= 1) {
            int i = ((t & ~(j - 1)) << 1) | (t & (j - 1));
            int p = i | j;
            unsigned long long a = sk[i], b = sk[p];
            bool up = ((i & k) == 0);
            if (up ? (a < b) : (a > b)) { sk[i] = b; sk[p] = a; }
            __syncthreads();
        }
    unsigned long long key = sk[t];
    g_vals[t] = __uint_as_float((unsigned)(key >> 32));
    g_idx[t] = 2047 - (int)(unsigned)(key & 0xFFFFFFFFull);
}

// ---------------- pooled 2-hop bits + dinvp + gather (merged), one pooled row per block ----------------
__global__ void k_pool2()
{
    __shared__ unsigned sbi[NW];
    __shared__ int ws[8];
    int i = blockIdx.x, t = threadIdx.x;
    int ii = g_idx[i];
    const unsigned* bi = g_bits + (size_t)ii * NW;
    if (t < NW) sbi[t] = bi[t];
    __syncthreads();
    int cnt = 0;
    for (int jb = 0; jb < KP; jb += 256) {
        int j = jb + t;
        const unsigned* bj = g_bits + (size_t)g_idx[j] * NW;
        bool c = false;
        for (int w = 0; w < NW && !c; w++) c = (sbi[w] & bj[w]) != 0u;
        unsigned word = __ballot_sync(~0u, c);
        cnt += c ? 1 : 0;
        if ((t & 31) == 0) g_bitsp[i * NWP + (j >> 5)] = word;
    }
    for (int o = 16; o; o >>= 1) cnt += __shfl_xor_sync(~0u, cnt, o);
    if ((t & 31) == 0) ws[t >> 5] = cnt;
    float vl = g_vals[i];
    int z = t >> 7, c = t & 127;
    g_catp[z][(size_t)i * 256 + c] = g_fg[z][(size_t)ii * 128 + c] * vl;
    __syncthreads();
    if (t == 0) {
        int s = 0;
        for (int k = 0; k < 8; k++) s += ws[k];
        g_dinvp[i] = rsqrtf((float)s);
    }
}

// ---------------- final: NCE combine for both stages + scalar ----------------
__global__ void k_final(float* __restrict__ out)
{
    int t = threadIdx.x;   // 1024 threads
    float sg = 0.f, sp = 0.f;
    for (int i = t; i < NN; i += 1024) {
        float s1 = 0.f, s2 = 0.f;
        for (int k = 0; k < 16; k++) { s1 += g_rp[k * NN + i]; s2 += g_cp[k * NN + i]; }
        sg += 2.f * INVT + __logf(s1) + __logf(s2) - 2.f * g_diag[i] * INVT;
    }
    {
        int i = t;
        float s1 = 0.f, s2 = 0.f;
        for (int k = 0; k < 8; k++) { s1 += g_rp2[k * KP + i]; s2 += g_cp2[k * KP + i]; }
        sp += 2.f * INVT + __logf(s1) + __logf(s2) - 2.f * g_diagp[i] * INVT;
    }
    for (int o = 16; o; o >>= 1) {
        sg += __shfl_xor_sync(~0u, sg, o);
        sp += __shfl_xor_sync(~0u, sp, o);
    }
    __shared__ float wg[32], wp[32];
    if ((t & 31) == 0) { wg[t >> 5] = sg; wp[t >> 5] = sp; }
    __syncthreads();
    if (t == 0) {
        float a = 0.f, b = 0.f;
        for (int i = 0; i < 32; i++) { a += wg[i]; b += wp[i]; }
        out[0] = a * (1.f / NN) + b * (1.f / KP);
    }
}

// ---------------- host ----------------
extern "C" void kernel_launch(void* const* d_in, const int* in_sizes, int n_in,
                              void* d_out, int out_size)
{
    (void)in_sizes; (void)n_in; (void)out_size;
    const float* fs    = (const float*)d_in[0];
    const float* ft    = (const float*)d_in[1];
    const float* We    = (const float*)d_in[2];
    const float* be    = (const float*)d_in[3];
    const float* Wg    = (const float*)d_in[4];
    const float* bg    = (const float*)d_in[5];
    const float* Wpool = (const float*)d_in[6];
    const float* bpool = (const float*)d_in[7];
    const float* Wgp   = (const float*)d_in[8];
    const float* bgp   = (const float*)d_in[9];

    void* p;
    cudaGetSymbolAddress(&p, g_fet);   float* FET  = (float*)p;
    cudaGetSymbolAddress(&p, g_fes);   float* FES  = (float*)p;
    cudaGetSymbolAddress(&p, g_bits);  unsigned* BITS  = (unsigned*)p;
    cudaGetSymbolAddress(&p, g_bitsp); unsigned* BITSP = (unsigned*)p;
    cudaGetSymbolAddress(&p, g_deg);   int*   DEG   = (int*)p;
    cudaGetSymbolAddress(&p, g_dinvp); float* DINVP = (float*)p;
    cudaGetSymbolAddress(&p, g_fg);    float* FG   = (float*)p;
    cudaGetSymbolAddress(&p, g_fp);    float* FP   = (float*)p;
    cudaGetSymbolAddress(&p, g_cat);   float* CAT  = (float*)p;
    cudaGetSymbolAddress(&p, g_catp);  float* CATP = (float*)p;
    cudaGetSymbolAddress(&p, g_part);  float* PART = (float*)p;
    cudaGetSymbolAddress(&p, g_rp);    float* RP   = (float*)p;
    cudaGetSymbolAddress(&p, g_cp);    float* CP   = (float*)p;
    cudaGetSymbolAddress(&p, g_rp2);   float* RP2  = (float*)p;
    cudaGetSymbolAddress(&p, g_cp2);   float* CP2  = (float*)p;
    cudaGetSymbolAddress(&p, g_diag);  float* DG1  = (float*)p;
    cudaGetSymbolAddress(&p, g_diagp); float* DG2  = (float*)p;

    const int ND = NN * DD;    // 262144
    const int KD = KP * DD;    // 131072
    const int CATLD = 384, CATPLD = 256;

    cudaStream_t sB;
    cudaEvent_t evF, evJ;
    cudaStreamCreateWithFlags(&sB, cudaStreamNonBlocking);
    cudaEventCreateWithFlags(&evF, cudaEventDisableTiming);
    cudaEventCreateWithFlags(&evJ, cudaEventDisableTiming);

    // 0) zero integer degrees (ordered before adjacency atomics on stream 0)
    cudaMemsetAsync(DEG, 0, NN * sizeof(int), 0);

    // 1) embed: f = l2norm(x @ We + be); z=0 teacher(ft), z=1 student(fs)
    k_mma_nn<<<dim3(16, 8, 2), 256>>>(ft, fs, CD, We, PART, NN, 64, 8);
    k_red_l2<<<dim3(NN / 4, 1, 2), 512>>>(PART, 8, ND, be, FET, FES, CAT, CAT + NN * CATLD, CATLD, (float*)0, (float*)0);

    // 2) adjacency bits from teacher gram (symmetric) + integer degrees via atomics
    k_mma_nt_adj<<<136, 256>>>(FET);

    // 3) TAGConv k=2 via binary MMA (dinv = rsqrt(deg) fused into B loader)
    k_mma_bin<1><<<dim3(16, 8, 2), 256>>>(BITS, NW, FET, FES, 128, (const float*)DEG, PART, NN, 256, 8);
    k_reduce_s4<1><<<dim3(ND / 1024, 1, 2), 256>>>(PART, 8, ND, CAT, CAT + NN * CATLD, CATLD, 128, (const float*)DEG);
    k_mma_bin<1><<<dim3(16, 8, 2), 256>>>(BITS, NW, CAT + 128, CAT + NN * CATLD + 128, CATLD, (const float*)DEG, PART, NN, 256, 8);
    k_reduce_s4<1><<<dim3(ND / 1024, 1, 2), 256>>>(PART, 8, ND, CAT, CAT + NN * CATLD, CATLD, 256, (const float*)DEG);

    // 4) concat GEMM (K=384, Kchunk=96) + bias + l2norm -> FG, + fused pooling scores (z=0)
    k_mma_nn<<<dim3(16, 4, 2), 256>>>(CAT, CAT + NN * CATLD, CATLD, Wg, PART, NN, 96, 4);
    k_red_l2<<<dim3(NN / 4, 1, 2), 512>>>(PART, 4, ND, bg, FG, FG + ND, (float*)0, (float*)0, 0, Wpool, bpool);

    // 5) stage-1 NCE on side stream, overlapped with the pooling chain
    cudaEventRecord(evF, 0);
    cudaStreamWaitEvent(sB, evF, 0);
    k_mma_nt_nce<<<dim3(16, 16), 256, 0, sB>>>(FG, FG + ND, NN, RP, CP, DG1);
    cudaEventRecord(evJ, sB);

    // 6) pooling: selection, then bits+dinvp+gather merged
    k_pool1<<<1, 1024>>>();
    k_pool2<<<KP, 256>>>();

    // 7) pooled TAGConv k=1 (dinvp fused into loader)
    k_mma_bin<0><<<dim3(8, 8, 2), 256>>>(BITSP, NWP, CATP, CATP + KP * CATPLD, CATPLD, DINVP, PART, KP, 128, 8);
    k_reduce_s4<0><<<dim3(KD / 1024, 1, 2), 256>>>(PART, 8, KD, CATP, CATP + KP * CATPLD, CATPLD, 128, DINVP);
    k_mma_nn<<<dim3(8, 4, 2), 256>>>(CATP, CATP + KP * CATPLD, CATPLD, Wgp, PART, KP, 64, 4);
    k_red_l2<<<dim3(KP / 4, 1, 2), 512>>>(PART, 4, KD, bgp, FP, FP + KD, (float*)0, (float*)0, 0, (float*)0, (float*)0);

    // 8) pooled NCE
    k_mma_nt_nce<<<dim3(8, 8), 256>>>(FP, FP + KD, KP, RP2, CP2, DG2);

    // 9) join + NCE combine (both stages) + final scalar
    cudaStreamWaitEvent(0, evJ, 0);
    k_final<<<1, 1024>>>((float*)d_out);
}